// round 13
// baseline (speedup 1.0000x reference)
#include <cuda_runtime.h>
#include <cuda_bf16.h>
#include <cuda_fp16.h>
#include <cstdint>

#define BB 8
#define CC 256
#define NN 2048

// ---------------- scratch (device globals; no allocs) ----------------------
__device__ __nv_bfloat16 g_Xh[BB * NN * CC];                       // xT [b][n][c]
__device__ __nv_bfloat16 g_Wh[3 * CC * CC];                        // Wq,Wk,Wv bf16
__device__ __nv_bfloat16 g_Qh[BB * NN * CC];                       // [b][n][c]
__device__ __nv_bfloat16 g_Kh[BB * NN * CC];                       // [b][m][c]
__device__ __nv_bfloat16 g_Vh[BB * CC * NN];                       // [b][c][m]
__device__ __half        g_S [(size_t)BB * NN * NN];               // fp16 scores
__device__ __nv_bfloat16 g_Ph[(size_t)BB * NN * NN];               // probs (bf16)

// ---------------- PTX helpers (baseline PTX only) ---------------------------
__device__ __forceinline__ uint32_t smem_u32(const void* p) {
    uint32_t a;
    asm("{ .reg .u64 t; cvta.to.shared.u64 t, %1; cvt.u32.u64 %0, t; }"
        : "=r"(a) : "l"(p));
    return a;
}

#define CP_ASYNC16(dst, src) \
    asm volatile("cp.async.cg.shared.global [%0], [%1], 16;" \
                 :: "r"(dst), "l"(src) : "memory")
#define CP_COMMIT() asm volatile("cp.async.commit_group;" ::: "memory")
#define CP_WAIT(n)  asm volatile("cp.async.wait_group %0;" :: "n"(n) : "memory")

#define LDSM_X4(r0, r1, r2, r3, addr) \
    asm volatile("ldmatrix.sync.aligned.m8n8.x4.shared.b16 {%0,%1,%2,%3}, [%4];" \
                 : "=r"(r0), "=r"(r1), "=r"(r2), "=r"(r3) : "r"(addr))

#define MMA16816(c, a, b0, b1) \
    asm volatile("mma.sync.aligned.m16n8k16.row.col.f32.bf16.bf16.f32 " \
                 "{%0,%1,%2,%3}, {%4,%5,%6,%7}, {%8,%9}, {%0,%1,%2,%3};" \
                 : "+f"((c)[0]), "+f"((c)[1]), "+f"((c)[2]), "+f"((c)[3]) \
                 : "r"((a)[0]), "r"((a)[1]), "r"((a)[2]), "r"((a)[3]), \
                   "r"(b0), "r"(b1))

__device__ __forceinline__ __nv_bfloat16 bsplit_hi(float v) { return __float2bfloat16(v); }

#define ROW_STRIDE 80
#define TILE_BYTES 10240            // 128 rows * 80 B
#define HTILE_BYTES 5120            // 64 rows * 80 B
// out gemm (old shape): BK=32, 3-stage ring, stage = [A(128)|B(128)]
#define S_STAGE    (2 * TILE_BYTES)         // 20480
#define G_SMEM     (3 * S_STAGE)            // 61440
// scores gemm (24-warp shape): stage = [A(128)|B(64)]
#define S24_STAGE  (TILE_BYTES + HTILE_BYTES)   // 15360
#define G24_SMEM   (3 * S24_STAGE)              // 46080
// qkv kernel smem
#define QB_TILE    5120
#define QBUF       (TILE_BYTES + 3 * QB_TILE)   // 25600
#define QSMEM      (2 * QBUF)                   // 51200

// ---------------------------------------------------------------------------
// xsplit: x [b][c][n] fp32 -> xT [b][n][c] bf16
// ---------------------------------------------------------------------------
__global__ __launch_bounds__(256) void xsplit_kernel(const float* __restrict__ x)
{
    __shared__ float t[32][33];
    const int n0 = blockIdx.x * 32;
    const int c0 = blockIdx.y * 32;
    const int b  = blockIdx.z;
    const int tx = threadIdx.x & 31;
    const int ty = threadIdx.x >> 5;

    #pragma unroll
    for (int k = 0; k < 4; k++)
        t[ty + k * 8][tx] = x[((size_t)b * CC + c0 + ty + k * 8) * NN + n0 + tx];
    __syncthreads();
    #pragma unroll
    for (int k = 0; k < 4; k++) {
        const float v = t[tx][ty + k * 8];
        const size_t idx = ((size_t)b * NN + n0 + ty + k * 8) * CC + c0 + tx;
        g_Xh[idx] = bsplit_hi(v);
    }
}

// ---------------------------------------------------------------------------
// wsplit: Wq/Wk/Wv fp32 -> bf16
// ---------------------------------------------------------------------------
__global__ __launch_bounds__(256) void wsplit_kernel(
    const float* __restrict__ Wq, const float* __restrict__ Wk,
    const float* __restrict__ Wv)
{
    const int m = blockIdx.y;
    const int e = blockIdx.x * 256 + threadIdx.x;
    const float v = (m == 0 ? Wq : (m == 1 ? Wk : Wv))[e];
    g_Wh[m * CC * CC + e] = bsplit_hi(v);
}

// ---------------------------------------------------------------------------
// qkv_mma: single-pass bf16 HMMA projection, fused Q/K/V (proven).
// ---------------------------------------------------------------------------
__global__ __launch_bounds__(256) void qkv_mma(
    const float* __restrict__ bq, const float* __restrict__ bk,
    const float* __restrict__ bv)
{
    extern __shared__ __align__(16) char sm[];
    const int n0 = blockIdx.x * 128;
    const int o0 = blockIdx.y * 64;
    const int b  = blockIdx.z;

    const int tid  = threadIdx.x;
    const int wid  = tid >> 5;
    const int lane = tid & 31;
    const int wn   = wid & 1;
    const int wm   = wid >> 1;

    const uint32_t smbase = smem_u32(sm);

    const __nv_bfloat16* gX = g_Xh + ((size_t)b * NN + n0) * CC;
    const __nv_bfloat16* W3[3] = { g_Wh, g_Wh + CC * CC, g_Wh + 2 * CC * CC };

    const uint32_t offA = (uint32_t)((lane & 15) * ROW_STRIDE + (lane >> 4) * 16);
    const uint32_t offB = (uint32_t)(((lane & 7) + ((lane >> 4) << 3)) * ROW_STRIDE
                                     + (((lane >> 3) & 1) << 4));

    float acc[3][2][4][4] = {};

    const int alr = tid >> 1, alc = (tid & 1) * 2;
    const int brb = tid >> 2, bcb = tid & 3;

    auto issue = [&](int buf, int k0) {
        const uint32_t base = smbase + buf * QBUF;
        #pragma unroll
        for (int c = 0; c < 2; c++) {
            const int chunk = alc + c;
            CP_ASYNC16(base + (uint32_t)(alr * ROW_STRIDE + chunk * 16),
                       gX + (size_t)alr * CC + k0 + chunk * 8);
        }
        const uint32_t sob = base + TILE_BYTES
                           + (uint32_t)(brb * ROW_STRIDE + bcb * 16);
        const size_t gwb = (size_t)(o0 + brb) * CC + k0 + bcb * 8;
        #pragma unroll
        for (int m = 0; m < 3; m++)
            CP_ASYNC16(sob + m * QB_TILE, W3[m] + gwb);
        CP_COMMIT();
    };

    issue(0, 0);
    issue(1, 32);

    #pragma unroll 1
    for (int t = 0; t < 8; t++) {
        if (t == 7) { CP_WAIT(0); } else { CP_WAIT(1); }
        __syncthreads();
        const uint32_t base = smbase + (t & 1) * QBUF;

        #pragma unroll
        for (int ks = 0; ks < 2; ks++) {
            const uint32_t kb2 = ks * 32;
            uint32_t ah[2][4];
            #pragma unroll
            for (int mt = 0; mt < 2; mt++) {
                const uint32_t toff = (uint32_t)((wm * 32 + mt * 16) * ROW_STRIDE) + kb2 + offA;
                LDSM_X4(ah[mt][0], ah[mt][1], ah[mt][2], ah[mt][3], base + toff);
            }
            #pragma unroll
            for (int q = 0; q < 3; q++) {
                uint32_t bh[4][2];
                #pragma unroll
                for (int g = 0; g < 2; g++) {
                    const uint32_t toffb = (uint32_t)((wn * 32 + g * 16) * ROW_STRIDE) + kb2 + offB;
                    LDSM_X4(bh[2*g][0], bh[2*g][1], bh[2*g+1][0], bh[2*g+1][1],
                            base + TILE_BYTES + q * QB_TILE + toffb);
                }
                #pragma unroll
                for (int mt = 0; mt < 2; mt++)
                    #pragma unroll
                    for (int nt = 0; nt < 4; nt++)
                        MMA16816(acc[q][mt][nt], ah[mt], bh[nt][0], bh[nt][1]);
            }
        }
        __syncthreads();
        if (t + 2 < 8) issue(t & 1, (t + 2) * 32);
    }

    const int g  = lane >> 2;
    const int tq = lane & 3;

    // Q, K stores [n][c]
    #pragma unroll
    for (int mt = 0; mt < 2; mt++)
        #pragma unroll
        for (int h = 0; h < 2; h++) {
            const int n = n0 + wm * 32 + mt * 16 + g + h * 8;
            #pragma unroll
            for (int nt = 0; nt < 4; nt++) {
                const int col = o0 + wn * 32 + nt * 8 + tq * 2;
                const size_t idx = ((size_t)b * NN + n) * CC + col;
                const float q0 = acc[0][mt][nt][2*h]   + bq[col];
                const float q1 = acc[0][mt][nt][2*h+1] + bq[col + 1];
                const float k0v = acc[1][mt][nt][2*h]   + bk[col];
                const float k1v = acc[1][mt][nt][2*h+1] + bk[col + 1];
                *(__nv_bfloat162*)&g_Qh[idx] = __halves2bfloat162(bsplit_hi(q0), bsplit_hi(q1));
                *(__nv_bfloat162*)&g_Kh[idx] = __halves2bfloat162(bsplit_hi(k0v), bsplit_hi(k1v));
            }
        }

    // V: stage fp32 in smem, transpose to [c][n]
    __syncthreads();
    float* vbuf = (float*)sm;
    #pragma unroll
    for (int mt = 0; mt < 2; mt++)
        #pragma unroll
        for (int h = 0; h < 2; h++) {
            const int row = wm * 32 + mt * 16 + g + h * 8;
            #pragma unroll
            for (int nt = 0; nt < 4; nt++) {
                const int col = wn * 32 + nt * 8 + tq * 2;
                vbuf[row * 65 + col]     = acc[2][mt][nt][2*h]   + bv[o0 + col];
                vbuf[row * 65 + col + 1] = acc[2][mt][nt][2*h+1] + bv[o0 + col + 1];
            }
        }
    __syncthreads();
    #pragma unroll
    for (int cr = 0; cr < 8; cr++) {
        const int c = wid * 8 + cr;
        const size_t obase = ((size_t)b * CC + o0 + c) * NN + n0;
        #pragma unroll
        for (int it = 0; it < 2; it++) {
            const int nl = it * 64 + lane * 2;
            const float f0 = vbuf[nl * 65 + c];
            const float f1 = vbuf[(nl + 1) * 65 + c];
            *(__nv_bfloat162*)&g_Vh[obase + nl]
                = __halves2bfloat162(bsplit_hi(f0), bsplit_hi(f1));
        }
    }
}

// ---------------------------------------------------------------------------
// 24-warp scores GEMM: CTA 128(m)x64(n), 256 thr (8 warps 4x2), warp 32x32.
// BK=32, 3-stage ring, launch_bounds(256,3) -> 3 CTA/SM = 24 warps.
//   S[i][j] = scale * sum_k A[i][k]*B[j][k], fp16 out.
// ---------------------------------------------------------------------------
template<int KTILES>
__global__ __launch_bounds__(256, 3) void score_gemm24(
    const __nv_bfloat16* __restrict__ A, const __nv_bfloat16* __restrict__ B,
    __half* __restrict__ C,
    int lda, int ldb, int ldc, float scale,
    size_t sA, size_t sB, size_t sC)
{
    extern __shared__ __align__(16) char sm[];

    const int j0 = blockIdx.x * 64;
    const int i0 = blockIdx.y * 128;
    const int b  = blockIdx.z;

    const int tid  = threadIdx.x;
    const int lane = tid & 31;
    const int wid  = tid >> 5;
    const int wm   = wid >> 1;        // 0..3 (32 m-rows each)
    const int wn   = wid & 1;         // 0..1 (32 n-cols each)

    const __nv_bfloat16* gA = A + (size_t)b * sA;
    const __nv_bfloat16* gB = B + (size_t)b * sB;

    const uint32_t smbase = smem_u32(sm);

    const uint32_t offA = (uint32_t)((lane & 15) * ROW_STRIDE + (lane >> 4) * 16);
    const uint32_t offB = (uint32_t)(((lane & 7) + ((lane >> 4) << 3)) * ROW_STRIDE
                                     + (((lane >> 3) & 1) << 4));

    float acc[2][4][4] = {};   // [mt][nt][reg]

    // loads: A 128 rows (2 thr/row, 2 chunks each), B 64 rows (4 thr/row, 1 chunk)
    const int alr = tid >> 1, alc = (tid & 1) * 2;
    const int brb = tid >> 2, bcb = tid & 3;

    auto issue = [&](int buf, int k0) {
        const uint32_t base = smbase + buf * S24_STAGE;
        #pragma unroll
        for (int c = 0; c < 2; c++) {
            const int chunk = alc + c;
            CP_ASYNC16(base + (uint32_t)(alr * ROW_STRIDE + chunk * 16),
                       gA + (size_t)(i0 + alr) * lda + k0 + chunk * 8);
        }
        CP_ASYNC16(base + TILE_BYTES + (uint32_t)(brb * ROW_STRIDE + bcb * 16),
                   gB + (size_t)(j0 + brb) * ldb + k0 + bcb * 8);
        CP_COMMIT();
    };

    issue(0, 0);
    issue(1, 32);

    int buf = 0;
    #pragma unroll 1
    for (int t = 0; t < KTILES; t++) {
        if (t == KTILES - 1) { CP_WAIT(0); } else { CP_WAIT(1); }
        __syncthreads();
        if (t + 2 < KTILES) {
            int pb = buf + 2; if (pb >= 3) pb -= 3;
            issue(pb, (t + 2) * 32);
        }

        const uint32_t aA = smbase + buf * S24_STAGE;
        const uint32_t aB = aA + TILE_BYTES;

        #pragma unroll
        for (int ks = 0; ks < 2; ks++) {
            const uint32_t kb2 = ks * 32;
            uint32_t ahf[2][4];
            #pragma unroll
            for (int mt = 0; mt < 2; mt++) {
                const uint32_t toff = (uint32_t)((wm * 32 + mt * 16) * ROW_STRIDE) + kb2 + offA;
                LDSM_X4(ahf[mt][0], ahf[mt][1], ahf[mt][2], ahf[mt][3], aA + toff);
            }
            uint32_t bhf[4][2];
            #pragma unroll
            for (int g = 0; g < 2; g++) {
                const uint32_t toff = (uint32_t)((wn * 32 + g * 16) * ROW_STRIDE) + kb2 + offB;
                LDSM_X4(bhf[2*g][0], bhf[2*g][1], bhf[2*g+1][0], bhf[2*g+1][1], aB + toff);
            }
            #pragma unroll
            for (int mt = 0; mt < 2; mt++)
                #pragma unroll
                for (int nt = 0; nt < 4; nt++)
                    MMA16816(acc[mt][nt], ahf[mt], bhf[nt][0], bhf[nt][1]);
        }

        buf = (buf + 1 == 3) ? 0 : buf + 1;
    }

    const int g  = lane >> 2;
    const int tq = lane & 3;
    __half* Cb = C + (size_t)b * sC;

    #pragma unroll
    for (int mt = 0; mt < 2; mt++) {
        const int row0 = i0 + wm * 32 + mt * 16 + g;
        #pragma unroll
        for (int nt = 0; nt < 4; nt++) {
            const int col = j0 + wn * 32 + nt * 8 + tq * 2;
            const size_t idx0 = (size_t)row0 * ldc + col;
            const size_t idx1 = (size_t)(row0 + 8) * ldc + col;
            *(__half2*)&Cb[idx0] = __floats2half2_rn(acc[mt][nt][0] * scale,
                                                     acc[mt][nt][1] * scale);
            *(__half2*)&Cb[idx1] = __floats2half2_rn(acc[mt][nt][2] * scale,
                                                     acc[mt][nt][3] * scale);
        }
    }
}

// ---------------------------------------------------------------------------
// out GEMM (proven R12 shape): BK=32, 3-stage, 256 thr, warp 64x32, fp32+resid.
// ---------------------------------------------------------------------------
template<int KTILES>
__global__ __launch_bounds__(256, 2) void out_gemm(
    const __nv_bfloat16* __restrict__ A, const __nv_bfloat16* __restrict__ B,
    float* __restrict__ C, const float* __restrict__ R,
    int lda, int ldb, int ldc,
    size_t sA, size_t sB, size_t sC)
{
    extern __shared__ __align__(16) char sm[];

    const int j0 = blockIdx.x * 128;
    const int i0 = blockIdx.y * 128;
    const int b  = blockIdx.z;

    const int tid  = threadIdx.x;
    const int lane = tid & 31;
    const int wid  = tid >> 5;
    const int wm   = wid >> 2;
    const int wn   = wid & 3;

    const __nv_bfloat16* gA = A + (size_t)b * sA;
    const __nv_bfloat16* gB = B + (size_t)b * sB;

    const int lr = tid >> 1;
    const int lc = (tid & 1) * 2;
    const uint32_t smbase = smem_u32(sm);

    const uint32_t offA = (uint32_t)((lane & 15) * ROW_STRIDE + (lane >> 4) * 16);
    const uint32_t offB = (uint32_t)(((lane & 7) + ((lane >> 4) << 3)) * ROW_STRIDE
                                     + (((lane >> 3) & 1) << 4));

    float acc[4][4][4] = {};

    auto issue = [&](int buf, int k0) {
        const uint32_t base = smbase + buf * S_STAGE;
        #pragma unroll
        for (int c = 0; c < 2; c++) {
            const int chunk = lc + c;
            const uint32_t so = base + (uint32_t)(lr * ROW_STRIDE + chunk * 16);
            CP_ASYNC16(so,              gA + (size_t)(i0 + lr) * lda + k0 + chunk * 8);
            CP_ASYNC16(so + TILE_BYTES, gB + (size_t)(j0 + lr) * ldb + k0 + chunk * 8);
        }
        CP_COMMIT();
    };

    issue(0, 0);
    issue(1, 32);

    int buf = 0;
    #pragma unroll 1
    for (int t = 0; t < KTILES; t++) {
        if (t == KTILES - 1) { CP_WAIT(0); } else { CP_WAIT(1); }
        __syncthreads();
        if (t + 2 < KTILES) {
            int pb = buf + 2; if (pb >= 3) pb -= 3;
            issue(pb, (t + 2) * 32);
        }

        const uint32_t aA = smbase + buf * S_STAGE;
        const uint32_t aB = aA + TILE_BYTES;

        #pragma unroll
        for (int ks = 0; ks < 2; ks++) {
            const uint32_t kb2 = ks * 32;
            uint32_t ahf[4][4];
            #pragma unroll
            for (int mt = 0; mt < 4; mt++) {
                const uint32_t toff = (uint32_t)((wm * 64 + mt * 16) * ROW_STRIDE) + kb2 + offA;
                LDSM_X4(ahf[mt][0], ahf[mt][1], ahf[mt][2], ahf[mt][3], aA + toff);
            }
            uint32_t bhf[4][2];
            #pragma unroll
            for (int g = 0; g < 2; g++) {
                const uint32_t toff = (uint32_t)((wn * 32 + g * 16) * ROW_STRIDE) + kb2 + offB;
                LDSM_X4(bhf[2*g][0], bhf[2*g][1], bhf[2*g+1][0], bhf[2*g+1][1], aB + toff);
            }
            #pragma unroll
            for (int mt = 0; mt < 4; mt++)
                #pragma unroll
                for (int nt = 0; nt < 4; nt++)
                    MMA16816(acc[mt][nt], ahf[mt], bhf[nt][0], bhf[nt][1]);
        }

        buf = (buf + 1 == 3) ? 0 : buf + 1;
    }

    const int g  = lane >> 2;
    const int tq = lane & 3;
    float* Cb = C + (size_t)b * sC;
    const float* Rb = R + (size_t)b * sC;

    #pragma unroll
    for (int mt = 0; mt < 4; mt++) {
        const int row0 = i0 + wm * 64 + mt * 16 + g;
        #pragma unroll
        for (int nt = 0; nt < 4; nt++) {
            const int col = j0 + wn * 32 + nt * 8 + tq * 2;
            float2 v0 = make_float2(acc[mt][nt][0], acc[mt][nt][1]);
            float2 v1 = make_float2(acc[mt][nt][2], acc[mt][nt][3]);
            const size_t idx0 = (size_t)row0 * ldc + col;
            const size_t idx1 = (size_t)(row0 + 8) * ldc + col;
            float2 r0 = *(const float2*)&Rb[idx0];
            float2 r1 = *(const float2*)&Rb[idx1];
            v0.x += r0.x; v0.y += r0.y; v1.x += r1.x; v1.y += r1.y;
            *(float2*)&Cb[idx0] = v0;
            *(float2*)&Cb[idx1] = v1;
        }
    }
}

// ---------------------------------------------------------------------------
// softmax: fp16 scores -> bf16 probs. One uint4 load/store per thread.
// ---------------------------------------------------------------------------
__global__ __launch_bounds__(256) void softmax_kernel()
{
    __shared__ float redmax[8];
    __shared__ float redsum[8];

    const size_t row = blockIdx.x;
    const __half* p = g_S + row * NN;
    __nv_bfloat16* ph = g_Ph + row * NN;
    const int tid  = threadIdx.x;
    const int lane = tid & 31;
    const int warp = tid >> 5;

    uint4 raw = *(const uint4*)&p[tid * 8];
    const __half2* hp = (const __half2*)&raw;
    float v[8];
    #pragma unroll
    for (int q = 0; q < 4; q++) {
        float2 f = __half22float2(hp[q]);
        v[2*q] = f.x; v[2*q+1] = f.y;
    }

    float mx = -3.4e38f;
    #pragma unroll
    for (int t = 0; t < 8; t++) mx = fmaxf(mx, v[t]);
    #pragma unroll
    for (int o = 16; o > 0; o >>= 1)
        mx = fmaxf(mx, __shfl_xor_sync(0xffffffffu, mx, o));
    if (lane == 0) redmax[warp] = mx;
    __syncthreads();
    if (warp == 0) {
        float w = (lane < 8) ? redmax[lane] : -3.4e38f;
        #pragma unroll
        for (int o = 4; o > 0; o >>= 1)
            w = fmaxf(w, __shfl_xor_sync(0xffffffffu, w, o));
        if (lane == 0) redmax[0] = w;
    }
    __syncthreads();
    mx = redmax[0];

    float s = 0.0f;
    #pragma unroll
    for (int t = 0; t < 8; t++) {
        v[t] = __expf(v[t] - mx);
        s += v[t];
    }
    #pragma unroll
    for (int o = 16; o > 0; o >>= 1)
        s += __shfl_xor_sync(0xffffffffu, s, o);
    if (lane == 0) redsum[warp] = s;
    __syncthreads();
    if (warp == 0) {
        float w = (lane < 8) ? redsum[lane] : 0.0f;
        #pragma unroll
        for (int o = 4; o > 0; o >>= 1)
            w += __shfl_xor_sync(0xffffffffu, w, o);
        if (lane == 0) redsum[0] = w;
    }
    __syncthreads();
    const float inv = 1.0f / redsum[0];

    uint4 outw;
    __nv_bfloat162* op = (__nv_bfloat162*)&outw;
    #pragma unroll
    for (int q = 0; q < 4; q++)
        op[q] = __halves2bfloat162(bsplit_hi(v[2*q] * inv), bsplit_hi(v[2*q+1] * inv));
    *(uint4*)&ph[tid * 8] = outw;
}

// ---------------------------------------------------------------------------
extern "C" void kernel_launch(void* const* d_in, const int* in_sizes, int n_in,
                              void* d_out, int out_size)
{
    const float* x  = (const float*)d_in[0];
    const float* Wq = (const float*)d_in[1];
    const float* bq = (const float*)d_in[2];
    const float* Wk = (const float*)d_in[3];
    const float* bk = (const float*)d_in[4];
    const float* Wv = (const float*)d_in[5];
    const float* bv = (const float*)d_in[6];
    float* out = (float*)d_out;

    void *pQh, *pKh, *pVh, *pS, *pPh;
    cudaGetSymbolAddress(&pQh, g_Qh);
    cudaGetSymbolAddress(&pKh, g_Kh);
    cudaGetSymbolAddress(&pVh, g_Vh);
    cudaGetSymbolAddress(&pS,  g_S);
    cudaGetSymbolAddress(&pPh, g_Ph);

    cudaFuncSetAttribute(qkv_mma,
                         cudaFuncAttributeMaxDynamicSharedMemorySize, QSMEM);
    cudaFuncSetAttribute((const void*)score_gemm24<CC / 32>,
                         cudaFuncAttributeMaxDynamicSharedMemorySize, G24_SMEM);
    cudaFuncSetAttribute((const void*)out_gemm<NN / 32>,
                         cudaFuncAttributeMaxDynamicSharedMemorySize, G_SMEM);

    xsplit_kernel<<<dim3(NN / 32, CC / 32, BB), 256>>>(x);
    wsplit_kernel<<<dim3(CC, 3), 256>>>(Wq, Wk, Wv);
    qkv_mma<<<dim3(NN / 128, CC / 64, BB), 256, QSMEM>>>(bq, bk, bv);

    // scores: S[n][m] = 1/16 * Q[n][:] . K[m][:]   (K=256) -> fp16, 24-warp shape
    score_gemm24<CC / 32><<<dim3(NN / 64, NN / 128, BB), 256, G24_SMEM>>>(
        (const __nv_bfloat16*)pQh, (const __nv_bfloat16*)pKh,
        (__half*)pS,
        CC, CC, NN, 1.0f / 16.0f,
        (size_t)NN * CC, (size_t)NN * CC, (size_t)NN * NN);

    softmax_kernel<<<BB * NN, 256>>>();

    // out: C[c][n] = V[c][:] . P[n][:]  (K=2048) + x
    out_gemm<NN / 32><<<dim3(NN / 128, CC / 128, BB), 256, G_SMEM>>>(
        (const __nv_bfloat16*)pVh, (const __nv_bfloat16*)pPh,
        out, x,
        NN, NN, NN,
        (size_t)CC * NN, (size_t)NN * NN, (size_t)CC * NN);
}

// round 14
// speedup vs baseline: 1.0993x; 1.0993x over previous
#include <cuda_runtime.h>
#include <cuda_bf16.h>
#include <cuda_fp16.h>
#include <cstdint>

#define BB 8
#define CC 256
#define NN 2048
#define JT (NN / 128)          // 16 score col-tiles per row

// ---------------- scratch (device globals; no allocs) ----------------------
__device__ __nv_bfloat16 g_Xh[BB * NN * CC];                       // xT [b][n][c]
__device__ __nv_bfloat16 g_Wh[3 * CC * CC];                        // Wq,Wk,Wv bf16
__device__ __nv_bfloat16 g_Qh[BB * NN * CC];                       // [b][n][c]
__device__ __nv_bfloat16 g_Kh[BB * NN * CC];                       // [b][m][c]
__device__ __nv_bfloat16 g_Vh[BB * CC * NN];                       // [b][c][m]
__device__ __nv_bfloat16 g_Ph[(size_t)BB * NN * NN];               // exp(S) (bf16, unnormalized)
__device__ float         g_lp[(size_t)BB * JT * NN];               // partial row sums
__device__ float         g_linv[BB * NN];                          // 1/rowsum

// ---------------- PTX helpers (baseline PTX only) ---------------------------
__device__ __forceinline__ uint32_t smem_u32(const void* p) {
    uint32_t a;
    asm("{ .reg .u64 t; cvta.to.shared.u64 t, %1; cvt.u32.u64 %0, t; }"
        : "=r"(a) : "l"(p));
    return a;
}

#define CP_ASYNC16(dst, src) \
    asm volatile("cp.async.cg.shared.global [%0], [%1], 16;" \
                 :: "r"(dst), "l"(src) : "memory")
#define CP_COMMIT() asm volatile("cp.async.commit_group;" ::: "memory")
#define CP_WAIT(n)  asm volatile("cp.async.wait_group %0;" :: "n"(n) : "memory")

#define LDSM_X4(r0, r1, r2, r3, addr) \
    asm volatile("ldmatrix.sync.aligned.m8n8.x4.shared.b16 {%0,%1,%2,%3}, [%4];" \
                 : "=r"(r0), "=r"(r1), "=r"(r2), "=r"(r3) : "r"(addr))

#define MMA16816(c, a, b0, b1) \
    asm volatile("mma.sync.aligned.m16n8k16.row.col.f32.bf16.bf16.f32 " \
                 "{%0,%1,%2,%3}, {%4,%5,%6,%7}, {%8,%9}, {%0,%1,%2,%3};" \
                 : "+f"((c)[0]), "+f"((c)[1]), "+f"((c)[2]), "+f"((c)[3]) \
                 : "r"((a)[0]), "r"((a)[1]), "r"((a)[2]), "r"((a)[3]), \
                   "r"(b0), "r"(b1))

__device__ __forceinline__ __nv_bfloat16 bsplit_hi(float v) { return __float2bfloat16(v); }

#define ROW_STRIDE 80
#define TILE_BYTES 10240            // 128 rows * 80 B
// gemm: BK=32, 3-stage ring, stage = [A(128)|B(128)]
#define S_STAGE    (2 * TILE_BYTES)         // 20480
#define G_SMEM     (3 * S_STAGE)            // 61440
// qkv kernel smem
#define QB_TILE    5120
#define QBUF       (TILE_BYTES + 3 * QB_TILE)   // 25600
#define QSMEM      (2 * QBUF)                   // 51200

// ---------------------------------------------------------------------------
// xsplit: x [b][c][n] fp32 -> xT [b][n][c] bf16
// ---------------------------------------------------------------------------
__global__ __launch_bounds__(256) void xsplit_kernel(const float* __restrict__ x)
{
    __shared__ float t[32][33];
    const int n0 = blockIdx.x * 32;
    const int c0 = blockIdx.y * 32;
    const int b  = blockIdx.z;
    const int tx = threadIdx.x & 31;
    const int ty = threadIdx.x >> 5;

    #pragma unroll
    for (int k = 0; k < 4; k++)
        t[ty + k * 8][tx] = x[((size_t)b * CC + c0 + ty + k * 8) * NN + n0 + tx];
    __syncthreads();
    #pragma unroll
    for (int k = 0; k < 4; k++) {
        const float v = t[tx][ty + k * 8];
        const size_t idx = ((size_t)b * NN + n0 + ty + k * 8) * CC + c0 + tx;
        g_Xh[idx] = bsplit_hi(v);
    }
}

// ---------------------------------------------------------------------------
// wsplit: Wq/Wk/Wv fp32 -> bf16
// ---------------------------------------------------------------------------
__global__ __launch_bounds__(256) void wsplit_kernel(
    const float* __restrict__ Wq, const float* __restrict__ Wk,
    const float* __restrict__ Wv)
{
    const int m = blockIdx.y;
    const int e = blockIdx.x * 256 + threadIdx.x;
    const float v = (m == 0 ? Wq : (m == 1 ? Wk : Wv))[e];
    g_Wh[m * CC * CC + e] = bsplit_hi(v);
}

// ---------------------------------------------------------------------------
// qkv_mma: single-pass bf16 HMMA projection, fused Q/K/V (proven).
// ---------------------------------------------------------------------------
__global__ __launch_bounds__(256) void qkv_mma(
    const float* __restrict__ bq, const float* __restrict__ bk,
    const float* __restrict__ bv)
{
    extern __shared__ __align__(16) char sm[];
    const int n0 = blockIdx.x * 128;
    const int o0 = blockIdx.y * 64;
    const int b  = blockIdx.z;

    const int tid  = threadIdx.x;
    const int wid  = tid >> 5;
    const int lane = tid & 31;
    const int wn   = wid & 1;
    const int wm   = wid >> 1;

    const uint32_t smbase = smem_u32(sm);

    const __nv_bfloat16* gX = g_Xh + ((size_t)b * NN + n0) * CC;
    const __nv_bfloat16* W3[3] = { g_Wh, g_Wh + CC * CC, g_Wh + 2 * CC * CC };

    const uint32_t offA = (uint32_t)((lane & 15) * ROW_STRIDE + (lane >> 4) * 16);
    const uint32_t offB = (uint32_t)(((lane & 7) + ((lane >> 4) << 3)) * ROW_STRIDE
                                     + (((lane >> 3) & 1) << 4));

    float acc[3][2][4][4] = {};

    const int alr = tid >> 1, alc = (tid & 1) * 2;
    const int brb = tid >> 2, bcb = tid & 3;

    auto issue = [&](int buf, int k0) {
        const uint32_t base = smbase + buf * QBUF;
        #pragma unroll
        for (int c = 0; c < 2; c++) {
            const int chunk = alc + c;
            CP_ASYNC16(base + (uint32_t)(alr * ROW_STRIDE + chunk * 16),
                       gX + (size_t)alr * CC + k0 + chunk * 8);
        }
        const uint32_t sob = base + TILE_BYTES
                           + (uint32_t)(brb * ROW_STRIDE + bcb * 16);
        const size_t gwb = (size_t)(o0 + brb) * CC + k0 + bcb * 8;
        #pragma unroll
        for (int m = 0; m < 3; m++)
            CP_ASYNC16(sob + m * QB_TILE, W3[m] + gwb);
        CP_COMMIT();
    };

    issue(0, 0);
    issue(1, 32);

    #pragma unroll 1
    for (int t = 0; t < 8; t++) {
        if (t == 7) { CP_WAIT(0); } else { CP_WAIT(1); }
        __syncthreads();
        const uint32_t base = smbase + (t & 1) * QBUF;

        #pragma unroll
        for (int ks = 0; ks < 2; ks++) {
            const uint32_t kb2 = ks * 32;
            uint32_t ah[2][4];
            #pragma unroll
            for (int mt = 0; mt < 2; mt++) {
                const uint32_t toff = (uint32_t)((wm * 32 + mt * 16) * ROW_STRIDE) + kb2 + offA;
                LDSM_X4(ah[mt][0], ah[mt][1], ah[mt][2], ah[mt][3], base + toff);
            }
            #pragma unroll
            for (int q = 0; q < 3; q++) {
                uint32_t bh[4][2];
                #pragma unroll
                for (int g = 0; g < 2; g++) {
                    const uint32_t toffb = (uint32_t)((wn * 32 + g * 16) * ROW_STRIDE) + kb2 + offB;
                    LDSM_X4(bh[2*g][0], bh[2*g][1], bh[2*g+1][0], bh[2*g+1][1],
                            base + TILE_BYTES + q * QB_TILE + toffb);
                }
                #pragma unroll
                for (int mt = 0; mt < 2; mt++)
                    #pragma unroll
                    for (int nt = 0; nt < 4; nt++)
                        MMA16816(acc[q][mt][nt], ah[mt], bh[nt][0], bh[nt][1]);
            }
        }
        __syncthreads();
        if (t + 2 < 8) issue(t & 1, (t + 2) * 32);
    }

    const int g  = lane >> 2;
    const int tq = lane & 3;

    // Q, K stores [n][c]
    #pragma unroll
    for (int mt = 0; mt < 2; mt++)
        #pragma unroll
        for (int h = 0; h < 2; h++) {
            const int n = n0 + wm * 32 + mt * 16 + g + h * 8;
            #pragma unroll
            for (int nt = 0; nt < 4; nt++) {
                const int col = o0 + wn * 32 + nt * 8 + tq * 2;
                const size_t idx = ((size_t)b * NN + n) * CC + col;
                const float q0 = acc[0][mt][nt][2*h]   + bq[col];
                const float q1 = acc[0][mt][nt][2*h+1] + bq[col + 1];
                const float k0v = acc[1][mt][nt][2*h]   + bk[col];
                const float k1v = acc[1][mt][nt][2*h+1] + bk[col + 1];
                *(__nv_bfloat162*)&g_Qh[idx] = __halves2bfloat162(bsplit_hi(q0), bsplit_hi(q1));
                *(__nv_bfloat162*)&g_Kh[idx] = __halves2bfloat162(bsplit_hi(k0v), bsplit_hi(k1v));
            }
        }

    // V: stage fp32 in smem, transpose to [c][n]
    __syncthreads();
    float* vbuf = (float*)sm;
    #pragma unroll
    for (int mt = 0; mt < 2; mt++)
        #pragma unroll
        for (int h = 0; h < 2; h++) {
            const int row = wm * 32 + mt * 16 + g + h * 8;
            #pragma unroll
            for (int nt = 0; nt < 4; nt++) {
                const int col = wn * 32 + nt * 8 + tq * 2;
                vbuf[row * 65 + col]     = acc[2][mt][nt][2*h]   + bv[o0 + col];
                vbuf[row * 65 + col + 1] = acc[2][mt][nt][2*h+1] + bv[o0 + col + 1];
            }
        }
    __syncthreads();
    #pragma unroll
    for (int cr = 0; cr < 8; cr++) {
        const int c = wid * 8 + cr;
        const size_t obase = ((size_t)b * CC + o0 + c) * NN + n0;
        #pragma unroll
        for (int it = 0; it < 2; it++) {
            const int nl = it * 64 + lane * 2;
            const float f0 = vbuf[nl * 65 + c];
            const float f1 = vbuf[(nl + 1) * 65 + c];
            *(__nv_bfloat162*)&g_Vh[obase + nl]
                = __halves2bfloat162(bsplit_hi(f0), bsplit_hi(f1));
        }
    }
}

// ---------------------------------------------------------------------------
// score_gemm: R12 gemm shape (BK=32, 3-stage, 256 thr, warp 64x32) with fused
// exp epilogue: Ph = exp(S/16) (bf16, unnormalized), row partial sums to g_lp.
// No max-subtraction: scaled logits ~N(0,1), max<~6 -> exp safe in fp32.
// ---------------------------------------------------------------------------
template<int KTILES>
__global__ __launch_bounds__(256, 2) void score_gemm(
    const __nv_bfloat16* __restrict__ A, const __nv_bfloat16* __restrict__ B,
    int lda, int ldb, int ldc, float scale,
    size_t sA, size_t sB, size_t sC)
{
    extern __shared__ __align__(16) char sm[];

    const int j0 = blockIdx.x * 128;   // cols m (sum index of softmax rows)
    const int i0 = blockIdx.y * 128;   // rows n (softmax rows)
    const int b  = blockIdx.z;
    const int jt = blockIdx.x;         // 0..JT-1

    const int tid  = threadIdx.x;
    const int lane = tid & 31;
    const int wid  = tid >> 5;
    const int wm   = wid >> 2;
    const int wn   = wid & 3;

    const __nv_bfloat16* gA = A + (size_t)b * sA;
    const __nv_bfloat16* gB = B + (size_t)b * sB;

    const int lr = tid >> 1;
    const int lc = (tid & 1) * 2;
    const uint32_t smbase = smem_u32(sm);

    const uint32_t offA = (uint32_t)((lane & 15) * ROW_STRIDE + (lane >> 4) * 16);
    const uint32_t offB = (uint32_t)(((lane & 7) + ((lane >> 4) << 3)) * ROW_STRIDE
                                     + (((lane >> 3) & 1) << 4));

    float acc[4][4][4] = {};

    auto issue = [&](int buf, int k0) {
        const uint32_t base = smbase + buf * S_STAGE;
        #pragma unroll
        for (int c = 0; c < 2; c++) {
            const int chunk = lc + c;
            const uint32_t so = base + (uint32_t)(lr * ROW_STRIDE + chunk * 16);
            CP_ASYNC16(so,              gA + (size_t)(i0 + lr) * lda + k0 + chunk * 8);
            CP_ASYNC16(so + TILE_BYTES, gB + (size_t)(j0 + lr) * ldb + k0 + chunk * 8);
        }
        CP_COMMIT();
    };

    issue(0, 0);
    issue(1, 32);

    int buf = 0;
    #pragma unroll 1
    for (int t = 0; t < KTILES; t++) {
        if (t == KTILES - 1) { CP_WAIT(0); } else { CP_WAIT(1); }
        __syncthreads();
        if (t + 2 < KTILES) {
            int pb = buf + 2; if (pb >= 3) pb -= 3;
            issue(pb, (t + 2) * 32);
        }

        const uint32_t aA = smbase + buf * S_STAGE;
        const uint32_t aB = aA + TILE_BYTES;

        #pragma unroll
        for (int ks = 0; ks < 2; ks++) {
            const uint32_t kb2 = ks * 32;
            uint32_t ahf[4][4];
            #pragma unroll
            for (int mt = 0; mt < 4; mt++) {
                const uint32_t toff = (uint32_t)((wm * 64 + mt * 16) * ROW_STRIDE) + kb2 + offA;
                LDSM_X4(ahf[mt][0], ahf[mt][1], ahf[mt][2], ahf[mt][3], aA + toff);
            }
            uint32_t bhf[4][2];
            #pragma unroll
            for (int g = 0; g < 2; g++) {
                const uint32_t toff = (uint32_t)((wn * 32 + g * 16) * ROW_STRIDE) + kb2 + offB;
                LDSM_X4(bhf[2*g][0], bhf[2*g][1], bhf[2*g+1][0], bhf[2*g+1][1], aB + toff);
            }
            #pragma unroll
            for (int mt = 0; mt < 4; mt++)
                #pragma unroll
                for (int nt = 0; nt < 4; nt++)
                    MMA16816(acc[mt][nt], ahf[mt], bhf[nt][0], bhf[nt][1]);
        }

        buf = (buf + 1 == 3) ? 0 : buf + 1;
    }

    // ---- epilogue: exp + store bf16 + deterministic row partial sums ----
    const int g  = lane >> 2;
    const int tq = lane & 3;
    __nv_bfloat16* Pb = g_Ph + (size_t)b * sC;

    __syncthreads();                       // stages dead; reuse smem
    float* ps = (float*)sm;                // [4 wn][128 rows], single writer each

    #pragma unroll
    for (int mt = 0; mt < 4; mt++) {
        const int rl0 = wm * 64 + mt * 16 + g;       // local row (h=0)
        float r0 = 0.f, r1 = 0.f;
        #pragma unroll
        for (int nt = 0; nt < 4; nt++) {
            const int col = j0 + wn * 32 + nt * 8 + tq * 2;
            const float e0 = __expf(acc[mt][nt][0] * scale);
            const float e1 = __expf(acc[mt][nt][1] * scale);
            const float e2 = __expf(acc[mt][nt][2] * scale);
            const float e3 = __expf(acc[mt][nt][3] * scale);
            *(__nv_bfloat162*)&Pb[(size_t)(i0 + rl0) * ldc + col]
                = __halves2bfloat162(bsplit_hi(e0), bsplit_hi(e1));
            *(__nv_bfloat162*)&Pb[(size_t)(i0 + rl0 + 8) * ldc + col]
                = __halves2bfloat162(bsplit_hi(e2), bsplit_hi(e3));
            r0 += e0 + e1;
            r1 += e2 + e3;
        }
        // quad reduce over tq
        r0 += __shfl_xor_sync(0xffffffffu, r0, 1);
        r0 += __shfl_xor_sync(0xffffffffu, r0, 2);
        r1 += __shfl_xor_sync(0xffffffffu, r1, 1);
        r1 += __shfl_xor_sync(0xffffffffu, r1, 2);
        if (tq == 0) {
            ps[wn * 128 + rl0]     = r0;
            ps[wn * 128 + rl0 + 8] = r1;
        }
    }
    __syncthreads();
    if (tid < 128) {
        const float s = ps[tid] + ps[128 + tid] + ps[256 + tid] + ps[384 + tid];
        g_lp[((size_t)b * JT + jt) * NN + i0 + tid] = s;
    }
}

// ---------------------------------------------------------------------------
// lreduce: g_linv[b][n] = 1 / sum_jt g_lp[b][jt][n]
// ---------------------------------------------------------------------------
__global__ __launch_bounds__(256) void lreduce_kernel()
{
    const int r = blockIdx.x * 256 + threadIdx.x;    // 0..BB*NN-1
    const int b = r / NN, n = r % NN;
    float s = 0.f;
    #pragma unroll
    for (int jt = 0; jt < JT; jt++)
        s += g_lp[((size_t)b * JT + jt) * NN + n];
    g_linv[r] = 1.0f / s;
}

// ---------------------------------------------------------------------------
// out GEMM (proven shape) + normalize-by-rowsum + residual.
//   out[c][n] = linv[n] * sum_m Ph[n][m] V[c][m] + x[c][n]
// ---------------------------------------------------------------------------
template<int KTILES>
__global__ __launch_bounds__(256, 2) void out_gemm(
    const __nv_bfloat16* __restrict__ A, const __nv_bfloat16* __restrict__ B,
    float* __restrict__ C, const float* __restrict__ R,
    int lda, int ldb, int ldc,
    size_t sA, size_t sB, size_t sC)
{
    extern __shared__ __align__(16) char sm[];

    const int j0 = blockIdx.x * 128;
    const int i0 = blockIdx.y * 128;
    const int b  = blockIdx.z;

    const int tid  = threadIdx.x;
    const int lane = tid & 31;
    const int wid  = tid >> 5;
    const int wm   = wid >> 2;
    const int wn   = wid & 3;

    const __nv_bfloat16* gA = A + (size_t)b * sA;
    const __nv_bfloat16* gB = B + (size_t)b * sB;

    const int lr = tid >> 1;
    const int lc = (tid & 1) * 2;
    const uint32_t smbase = smem_u32(sm);

    const uint32_t offA = (uint32_t)((lane & 15) * ROW_STRIDE + (lane >> 4) * 16);
    const uint32_t offB = (uint32_t)(((lane & 7) + ((lane >> 4) << 3)) * ROW_STRIDE
                                     + (((lane >> 3) & 1) << 4));

    float acc[4][4][4] = {};

    auto issue = [&](int buf, int k0) {
        const uint32_t base = smbase + buf * S_STAGE;
        #pragma unroll
        for (int c = 0; c < 2; c++) {
            const int chunk = lc + c;
            const uint32_t so = base + (uint32_t)(lr * ROW_STRIDE + chunk * 16);
            CP_ASYNC16(so,              gA + (size_t)(i0 + lr) * lda + k0 + chunk * 8);
            CP_ASYNC16(so + TILE_BYTES, gB + (size_t)(j0 + lr) * ldb + k0 + chunk * 8);
        }
        CP_COMMIT();
    };

    issue(0, 0);
    issue(1, 32);

    int buf = 0;
    #pragma unroll 1
    for (int t = 0; t < KTILES; t++) {
        if (t == KTILES - 1) { CP_WAIT(0); } else { CP_WAIT(1); }
        __syncthreads();
        if (t + 2 < KTILES) {
            int pb = buf + 2; if (pb >= 3) pb -= 3;
            issue(pb, (t + 2) * 32);
        }

        const uint32_t aA = smbase + buf * S_STAGE;
        const uint32_t aB = aA + TILE_BYTES;

        #pragma unroll
        for (int ks = 0; ks < 2; ks++) {
            const uint32_t kb2 = ks * 32;
            uint32_t ahf[4][4];
            #pragma unroll
            for (int mt = 0; mt < 4; mt++) {
                const uint32_t toff = (uint32_t)((wm * 64 + mt * 16) * ROW_STRIDE) + kb2 + offA;
                LDSM_X4(ahf[mt][0], ahf[mt][1], ahf[mt][2], ahf[mt][3], aA + toff);
            }
            uint32_t bhf[4][2];
            #pragma unroll
            for (int g = 0; g < 2; g++) {
                const uint32_t toff = (uint32_t)((wn * 32 + g * 16) * ROW_STRIDE) + kb2 + offB;
                LDSM_X4(bhf[2*g][0], bhf[2*g][1], bhf[2*g+1][0], bhf[2*g+1][1], aB + toff);
            }
            #pragma unroll
            for (int mt = 0; mt < 4; mt++)
                #pragma unroll
                for (int nt = 0; nt < 4; nt++)
                    MMA16816(acc[mt][nt], ahf[mt], bhf[nt][0], bhf[nt][1]);
        }

        buf = (buf + 1 == 3) ? 0 : buf + 1;
    }

    const int g  = lane >> 2;
    const int tq = lane & 3;
    float* Cb = C + (size_t)b * sC;
    const float* Rb = R + (size_t)b * sC;
    const float* Lb = g_linv + b * NN;

    #pragma unroll
    for (int mt = 0; mt < 4; mt++) {
        const int row0 = i0 + wm * 64 + mt * 16 + g;
        #pragma unroll
        for (int nt = 0; nt < 4; nt++) {
            const int col = j0 + wn * 32 + nt * 8 + tq * 2;
            const float2 li = *(const float2*)&Lb[col];
            float2 v0 = make_float2(acc[mt][nt][0] * li.x, acc[mt][nt][1] * li.y);
            float2 v1 = make_float2(acc[mt][nt][2] * li.x, acc[mt][nt][3] * li.y);
            const size_t idx0 = (size_t)row0 * ldc + col;
            const size_t idx1 = (size_t)(row0 + 8) * ldc + col;
            float2 r0 = *(const float2*)&Rb[idx0];
            float2 r1 = *(const float2*)&Rb[idx1];
            v0.x += r0.x; v0.y += r0.y; v1.x += r1.x; v1.y += r1.y;
            *(float2*)&Cb[idx0] = v0;
            *(float2*)&Cb[idx1] = v1;
        }
    }
}

// ---------------------------------------------------------------------------
extern "C" void kernel_launch(void* const* d_in, const int* in_sizes, int n_in,
                              void* d_out, int out_size)
{
    const float* x  = (const float*)d_in[0];
    const float* Wq = (const float*)d_in[1];
    const float* bq = (const float*)d_in[2];
    const float* Wk = (const float*)d_in[3];
    const float* bk = (const float*)d_in[4];
    const float* Wv = (const float*)d_in[5];
    const float* bv = (const float*)d_in[6];
    float* out = (float*)d_out;

    void *pQh, *pKh, *pVh, *pPh;
    cudaGetSymbolAddress(&pQh, g_Qh);
    cudaGetSymbolAddress(&pKh, g_Kh);
    cudaGetSymbolAddress(&pVh, g_Vh);
    cudaGetSymbolAddress(&pPh, g_Ph);

    cudaFuncSetAttribute(qkv_mma,
                         cudaFuncAttributeMaxDynamicSharedMemorySize, QSMEM);
    cudaFuncSetAttribute((const void*)score_gemm<CC / 32>,
                         cudaFuncAttributeMaxDynamicSharedMemorySize, G_SMEM);
    cudaFuncSetAttribute((const void*)out_gemm<NN / 32>,
                         cudaFuncAttributeMaxDynamicSharedMemorySize, G_SMEM);

    xsplit_kernel<<<dim3(NN / 32, CC / 32, BB), 256>>>(x);
    wsplit_kernel<<<dim3(CC, 3), 256>>>(Wq, Wk, Wv);
    qkv_mma<<<dim3(NN / 128, CC / 64, BB), 256, QSMEM>>>(bq, bk, bv);

    // scores + exp: Ph[n][m] = exp(Q.K/16), row partials to g_lp
    score_gemm<CC / 32><<<dim3(NN / 128, NN / 128, BB), 256, G_SMEM>>>(
        (const __nv_bfloat16*)pQh, (const __nv_bfloat16*)pKh,
        CC, CC, NN, 1.0f / 16.0f,
        (size_t)NN * CC, (size_t)NN * CC, (size_t)NN * NN);

    lreduce_kernel<<<BB * NN / 256, 256>>>();

    // out: C[c][n] = linv[n] * (V[c][:] . Ph[n][:]) + x
    out_gemm<NN / 32><<<dim3(NN / 128, CC / 128, BB), 256, G_SMEM>>>(
        (const __nv_bfloat16*)pVh, (const __nv_bfloat16*)pPh,
        out, x,
        NN, NN, NN,
        (size_t)CC * NN, (size_t)NN * NN, (size_t)CC * NN);
}

// round 15
// speedup vs baseline: 1.1308x; 1.0287x over previous
#include <cuda_runtime.h>
#include <cuda_bf16.h>
#include <cuda_fp16.h>
#include <cstdint>

#define BB 8
#define CC 256
#define NN 2048
#define JT (NN / 128)          // 16 score col-tiles per row
#define NSLOT (4 * JT)         // 64 partial slots per row

// ---------------- scratch (device globals; no allocs) ----------------------
__device__ __nv_bfloat16 g_Xh[BB * NN * CC];                       // xT [b][n][c]
__device__ __nv_bfloat16 g_Wh[3 * CC * CC];                        // Wq,Wk,Wv bf16
__device__ __nv_bfloat16 g_Qh[BB * NN * CC];                       // [b][n][c]
__device__ __nv_bfloat16 g_Kh[BB * NN * CC];                       // [b][m][c]
__device__ __nv_bfloat16 g_Vh[BB * CC * NN];                       // [b][c][m]
__device__ __nv_bfloat16 g_Ph[(size_t)BB * NN * NN];               // exp(S) (bf16, unnormalized)
__device__ float         g_lp[(size_t)BB * NSLOT * NN];            // partial row sums

// ---------------- PTX helpers (baseline PTX only) ---------------------------
__device__ __forceinline__ uint32_t smem_u32(const void* p) {
    uint32_t a;
    asm("{ .reg .u64 t; cvta.to.shared.u64 t, %1; cvt.u32.u64 %0, t; }"
        : "=r"(a) : "l"(p));
    return a;
}

#define CP_ASYNC16(dst, src) \
    asm volatile("cp.async.cg.shared.global [%0], [%1], 16;" \
                 :: "r"(dst), "l"(src) : "memory")
#define CP_COMMIT() asm volatile("cp.async.commit_group;" ::: "memory")
#define CP_WAIT(n)  asm volatile("cp.async.wait_group %0;" :: "n"(n) : "memory")

#define LDSM_X4(r0, r1, r2, r3, addr) \
    asm volatile("ldmatrix.sync.aligned.m8n8.x4.shared.b16 {%0,%1,%2,%3}, [%4];" \
                 : "=r"(r0), "=r"(r1), "=r"(r2), "=r"(r3) : "r"(addr))

#define MMA16816(c, a, b0, b1) \
    asm volatile("mma.sync.aligned.m16n8k16.row.col.f32.bf16.bf16.f32 " \
                 "{%0,%1,%2,%3}, {%4,%5,%6,%7}, {%8,%9}, {%0,%1,%2,%3};" \
                 : "+f"((c)[0]), "+f"((c)[1]), "+f"((c)[2]), "+f"((c)[3]) \
                 : "r"((a)[0]), "r"((a)[1]), "r"((a)[2]), "r"((a)[3]), \
                   "r"(b0), "r"(b1))

__device__ __forceinline__ __nv_bfloat16 bsplit_hi(float v) { return __float2bfloat16(v); }

#define ROW_STRIDE 80
#define TILE_BYTES 10240            // 128 rows * 80 B
// gemm: BK=32, 3-stage ring, stage = [A(128)|B(128)]
#define S_STAGE    (2 * TILE_BYTES)         // 20480
#define G_SMEM     (3 * S_STAGE)            // 61440
// qkv kernel smem
#define QB_TILE    5120
#define QBUF       (TILE_BYTES + 3 * QB_TILE)   // 25600
#define QSMEM      (2 * QBUF)                   // 51200

// ---------------------------------------------------------------------------
// xsplit: x [b][c][n] fp32 -> xT [b][n][c] bf16
// ---------------------------------------------------------------------------
__global__ __launch_bounds__(256) void xsplit_kernel(const float* __restrict__ x)
{
    __shared__ float t[32][33];
    const int n0 = blockIdx.x * 32;
    const int c0 = blockIdx.y * 32;
    const int b  = blockIdx.z;
    const int tx = threadIdx.x & 31;
    const int ty = threadIdx.x >> 5;

    #pragma unroll
    for (int k = 0; k < 4; k++)
        t[ty + k * 8][tx] = x[((size_t)b * CC + c0 + ty + k * 8) * NN + n0 + tx];
    __syncthreads();
    #pragma unroll
    for (int k = 0; k < 4; k++) {
        const float v = t[tx][ty + k * 8];
        const size_t idx = ((size_t)b * NN + n0 + ty + k * 8) * CC + c0 + tx;
        g_Xh[idx] = bsplit_hi(v);
    }
}

// ---------------------------------------------------------------------------
// wsplit: Wq/Wk/Wv fp32 -> bf16
// ---------------------------------------------------------------------------
__global__ __launch_bounds__(256) void wsplit_kernel(
    const float* __restrict__ Wq, const float* __restrict__ Wk,
    const float* __restrict__ Wv)
{
    const int m = blockIdx.y;
    const int e = blockIdx.x * 256 + threadIdx.x;
    const float v = (m == 0 ? Wq : (m == 1 ? Wk : Wv))[e];
    g_Wh[m * CC * CC + e] = bsplit_hi(v);
}

// ---------------------------------------------------------------------------
// qkv_mma: single-pass bf16 HMMA projection, fused Q/K/V (proven).
// ---------------------------------------------------------------------------
__global__ __launch_bounds__(256) void qkv_mma(
    const float* __restrict__ bq, const float* __restrict__ bk,
    const float* __restrict__ bv)
{
    extern __shared__ __align__(16) char sm[];
    const int n0 = blockIdx.x * 128;
    const int o0 = blockIdx.y * 64;
    const int b  = blockIdx.z;

    const int tid  = threadIdx.x;
    const int wid  = tid >> 5;
    const int lane = tid & 31;
    const int wn   = wid & 1;
    const int wm   = wid >> 1;

    const uint32_t smbase = smem_u32(sm);

    const __nv_bfloat16* gX = g_Xh + ((size_t)b * NN + n0) * CC;
    const __nv_bfloat16* W3[3] = { g_Wh, g_Wh + CC * CC, g_Wh + 2 * CC * CC };

    const uint32_t offA = (uint32_t)((lane & 15) * ROW_STRIDE + (lane >> 4) * 16);
    const uint32_t offB = (uint32_t)(((lane & 7) + ((lane >> 4) << 3)) * ROW_STRIDE
                                     + (((lane >> 3) & 1) << 4));

    float acc[3][2][4][4] = {};

    const int alr = tid >> 1, alc = (tid & 1) * 2;
    const int brb = tid >> 2, bcb = tid & 3;

    auto issue = [&](int buf, int k0) {
        const uint32_t base = smbase + buf * QBUF;
        #pragma unroll
        for (int c = 0; c < 2; c++) {
            const int chunk = alc + c;
            CP_ASYNC16(base + (uint32_t)(alr * ROW_STRIDE + chunk * 16),
                       gX + (size_t)alr * CC + k0 + chunk * 8);
        }
        const uint32_t sob = base + TILE_BYTES
                           + (uint32_t)(brb * ROW_STRIDE + bcb * 16);
        const size_t gwb = (size_t)(o0 + brb) * CC + k0 + bcb * 8;
        #pragma unroll
        for (int m = 0; m < 3; m++)
            CP_ASYNC16(sob + m * QB_TILE, W3[m] + gwb);
        CP_COMMIT();
    };

    issue(0, 0);
    issue(1, 32);

    #pragma unroll 1
    for (int t = 0; t < 8; t++) {
        if (t == 7) { CP_WAIT(0); } else { CP_WAIT(1); }
        __syncthreads();
        const uint32_t base = smbase + (t & 1) * QBUF;

        #pragma unroll
        for (int ks = 0; ks < 2; ks++) {
            const uint32_t kb2 = ks * 32;
            uint32_t ah[2][4];
            #pragma unroll
            for (int mt = 0; mt < 2; mt++) {
                const uint32_t toff = (uint32_t)((wm * 32 + mt * 16) * ROW_STRIDE) + kb2 + offA;
                LDSM_X4(ah[mt][0], ah[mt][1], ah[mt][2], ah[mt][3], base + toff);
            }
            #pragma unroll
            for (int q = 0; q < 3; q++) {
                uint32_t bh[4][2];
                #pragma unroll
                for (int g = 0; g < 2; g++) {
                    const uint32_t toffb = (uint32_t)((wn * 32 + g * 16) * ROW_STRIDE) + kb2 + offB;
                    LDSM_X4(bh[2*g][0], bh[2*g][1], bh[2*g+1][0], bh[2*g+1][1],
                            base + TILE_BYTES + q * QB_TILE + toffb);
                }
                #pragma unroll
                for (int mt = 0; mt < 2; mt++)
                    #pragma unroll
                    for (int nt = 0; nt < 4; nt++)
                        MMA16816(acc[q][mt][nt], ah[mt], bh[nt][0], bh[nt][1]);
            }
        }
        __syncthreads();
        if (t + 2 < 8) issue(t & 1, (t + 2) * 32);
    }

    const int g  = lane >> 2;
    const int tq = lane & 3;

    // Q, K stores [n][c]
    #pragma unroll
    for (int mt = 0; mt < 2; mt++)
        #pragma unroll
        for (int h = 0; h < 2; h++) {
            const int n = n0 + wm * 32 + mt * 16 + g + h * 8;
            #pragma unroll
            for (int nt = 0; nt < 4; nt++) {
                const int col = o0 + wn * 32 + nt * 8 + tq * 2;
                const size_t idx = ((size_t)b * NN + n) * CC + col;
                const float q0 = acc[0][mt][nt][2*h]   + bq[col];
                const float q1 = acc[0][mt][nt][2*h+1] + bq[col + 1];
                const float k0v = acc[1][mt][nt][2*h]   + bk[col];
                const float k1v = acc[1][mt][nt][2*h+1] + bk[col + 1];
                *(__nv_bfloat162*)&g_Qh[idx] = __halves2bfloat162(bsplit_hi(q0), bsplit_hi(q1));
                *(__nv_bfloat162*)&g_Kh[idx] = __halves2bfloat162(bsplit_hi(k0v), bsplit_hi(k1v));
            }
        }

    // V: stage fp32 in smem, transpose to [c][n]
    __syncthreads();
    float* vbuf = (float*)sm;
    #pragma unroll
    for (int mt = 0; mt < 2; mt++)
        #pragma unroll
        for (int h = 0; h < 2; h++) {
            const int row = wm * 32 + mt * 16 + g + h * 8;
            #pragma unroll
            for (int nt = 0; nt < 4; nt++) {
                const int col = wn * 32 + nt * 8 + tq * 2;
                vbuf[row * 65 + col]     = acc[2][mt][nt][2*h]   + bv[o0 + col];
                vbuf[row * 65 + col + 1] = acc[2][mt][nt][2*h+1] + bv[o0 + col + 1];
            }
        }
    __syncthreads();
    #pragma unroll
    for (int cr = 0; cr < 8; cr++) {
        const int c = wid * 8 + cr;
        const size_t obase = ((size_t)b * CC + o0 + c) * NN + n0;
        #pragma unroll
        for (int it = 0; it < 2; it++) {
            const int nl = it * 64 + lane * 2;
            const float f0 = vbuf[nl * 65 + c];
            const float f1 = vbuf[(nl + 1) * 65 + c];
            *(__nv_bfloat162*)&g_Vh[obase + nl]
                = __halves2bfloat162(bsplit_hi(f0), bsplit_hi(f1));
        }
    }
}

// ---------------------------------------------------------------------------
// score_gemm: proven gemm shape + fused exp epilogue.
// Ph = exp(S/16) (bf16, unnormalized); per-(jt,wn) row partials straight to
// g_lp (single writer per slot — deterministic, no smem combine).
// ---------------------------------------------------------------------------
template<int KTILES>
__global__ __launch_bounds__(256, 2) void score_gemm(
    const __nv_bfloat16* __restrict__ A, const __nv_bfloat16* __restrict__ B,
    int lda, int ldb, int ldc, float scale,
    size_t sA, size_t sB, size_t sC)
{
    extern __shared__ __align__(16) char sm[];

    const int j0 = blockIdx.x * 128;   // cols m
    const int i0 = blockIdx.y * 128;   // rows n (softmax rows)
    const int b  = blockIdx.z;
    const int jt = blockIdx.x;         // 0..JT-1

    const int tid  = threadIdx.x;
    const int lane = tid & 31;
    const int wid  = tid >> 5;
    const int wm   = wid >> 2;
    const int wn   = wid & 3;

    const __nv_bfloat16* gA = A + (size_t)b * sA;
    const __nv_bfloat16* gB = B + (size_t)b * sB;

    const int lr = tid >> 1;
    const int lc = (tid & 1) * 2;
    const uint32_t smbase = smem_u32(sm);

    const uint32_t offA = (uint32_t)((lane & 15) * ROW_STRIDE + (lane >> 4) * 16);
    const uint32_t offB = (uint32_t)(((lane & 7) + ((lane >> 4) << 3)) * ROW_STRIDE
                                     + (((lane >> 3) & 1) << 4));

    float acc[4][4][4] = {};

    auto issue = [&](int buf, int k0) {
        const uint32_t base = smbase + buf * S_STAGE;
        #pragma unroll
        for (int c = 0; c < 2; c++) {
            const int chunk = lc + c;
            const uint32_t so = base + (uint32_t)(lr * ROW_STRIDE + chunk * 16);
            CP_ASYNC16(so,              gA + (size_t)(i0 + lr) * lda + k0 + chunk * 8);
            CP_ASYNC16(so + TILE_BYTES, gB + (size_t)(j0 + lr) * ldb + k0 + chunk * 8);
        }
        CP_COMMIT();
    };

    issue(0, 0);
    issue(1, 32);

    int buf = 0;
    #pragma unroll 1
    for (int t = 0; t < KTILES; t++) {
        if (t == KTILES - 1) { CP_WAIT(0); } else { CP_WAIT(1); }
        __syncthreads();
        if (t + 2 < KTILES) {
            int pb = buf + 2; if (pb >= 3) pb -= 3;
            issue(pb, (t + 2) * 32);
        }

        const uint32_t aA = smbase + buf * S_STAGE;
        const uint32_t aB = aA + TILE_BYTES;

        #pragma unroll
        for (int ks = 0; ks < 2; ks++) {
            const uint32_t kb2 = ks * 32;
            uint32_t ahf[4][4];
            #pragma unroll
            for (int mt = 0; mt < 4; mt++) {
                const uint32_t toff = (uint32_t)((wm * 64 + mt * 16) * ROW_STRIDE) + kb2 + offA;
                LDSM_X4(ahf[mt][0], ahf[mt][1], ahf[mt][2], ahf[mt][3], aA + toff);
            }
            uint32_t bhf[4][2];
            #pragma unroll
            for (int g = 0; g < 2; g++) {
                const uint32_t toff = (uint32_t)((wn * 32 + g * 16) * ROW_STRIDE) + kb2 + offB;
                LDSM_X4(bhf[2*g][0], bhf[2*g][1], bhf[2*g+1][0], bhf[2*g+1][1], aB + toff);
            }
            #pragma unroll
            for (int mt = 0; mt < 4; mt++)
                #pragma unroll
                for (int nt = 0; nt < 4; nt++)
                    MMA16816(acc[mt][nt], ahf[mt], bhf[nt][0], bhf[nt][1]);
        }

        buf = (buf + 1 == 3) ? 0 : buf + 1;
    }

    // ---- epilogue: exp + bf16 store + direct per-slot partial sums ----
    const int g  = lane >> 2;
    const int tq = lane & 3;
    __nv_bfloat16* Pb = g_Ph + (size_t)b * sC;
    float* lpSlot = g_lp + ((size_t)b * NSLOT + (size_t)jt * 4 + wn) * NN + i0;

    #pragma unroll
    for (int mt = 0; mt < 4; mt++) {
        const int rl0 = wm * 64 + mt * 16 + g;
        float r0 = 0.f, r1 = 0.f;
        #pragma unroll
        for (int nt = 0; nt < 4; nt++) {
            const int col = j0 + wn * 32 + nt * 8 + tq * 2;
            const float e0 = __expf(acc[mt][nt][0] * scale);
            const float e1 = __expf(acc[mt][nt][1] * scale);
            const float e2 = __expf(acc[mt][nt][2] * scale);
            const float e3 = __expf(acc[mt][nt][3] * scale);
            *(__nv_bfloat162*)&Pb[(size_t)(i0 + rl0) * ldc + col]
                = __halves2bfloat162(bsplit_hi(e0), bsplit_hi(e1));
            *(__nv_bfloat162*)&Pb[(size_t)(i0 + rl0 + 8) * ldc + col]
                = __halves2bfloat162(bsplit_hi(e2), bsplit_hi(e3));
            r0 += e0 + e1;
            r1 += e2 + e3;
        }
        r0 += __shfl_xor_sync(0xffffffffu, r0, 1);
        r0 += __shfl_xor_sync(0xffffffffu, r0, 2);
        r1 += __shfl_xor_sync(0xffffffffu, r1, 1);
        r1 += __shfl_xor_sync(0xffffffffu, r1, 2);
        if (tq == 0) {
            lpSlot[rl0]     = r0;
            lpSlot[rl0 + 8] = r1;
        }
    }
}

// ---------------------------------------------------------------------------
// out GEMM (proven shape) + in-prologue rowsum reduce + normalize + residual.
//   out[c][n] = linv[n] * sum_m Ph[n][m] V[c][m] + x[c][n]
// ---------------------------------------------------------------------------
template<int KTILES>
__global__ __launch_bounds__(256, 2) void out_gemm(
    const __nv_bfloat16* __restrict__ A, const __nv_bfloat16* __restrict__ B,
    float* __restrict__ C, const float* __restrict__ R,
    int lda, int ldb, int ldc,
    size_t sA, size_t sB, size_t sC)
{
    extern __shared__ __align__(16) char sm[];
    __shared__ float linv_s[128];

    const int j0 = blockIdx.x * 128;   // n columns
    const int i0 = blockIdx.y * 128;   // c rows
    const int b  = blockIdx.z;

    const int tid  = threadIdx.x;
    const int lane = tid & 31;
    const int wid  = tid >> 5;
    const int wm   = wid >> 2;
    const int wn   = wid & 3;

    const __nv_bfloat16* gA = A + (size_t)b * sA;
    const __nv_bfloat16* gB = B + (size_t)b * sB;

    const int lr = tid >> 1;
    const int lc = (tid & 1) * 2;
    const uint32_t smbase = smem_u32(sm);

    const uint32_t offA = (uint32_t)((lane & 15) * ROW_STRIDE + (lane >> 4) * 16);
    const uint32_t offB = (uint32_t)(((lane & 7) + ((lane >> 4) << 3)) * ROW_STRIDE
                                     + (((lane >> 3) & 1) << 4));

    float acc[4][4][4] = {};

    auto issue = [&](int buf, int k0) {
        const uint32_t base = smbase + buf * S_STAGE;
        #pragma unroll
        for (int c = 0; c < 2; c++) {
            const int chunk = lc + c;
            const uint32_t so = base + (uint32_t)(lr * ROW_STRIDE + chunk * 16);
            CP_ASYNC16(so,              gA + (size_t)(i0 + lr) * lda + k0 + chunk * 8);
            CP_ASYNC16(so + TILE_BYTES, gB + (size_t)(j0 + lr) * ldb + k0 + chunk * 8);
        }
        CP_COMMIT();
    };

    issue(0, 0);
    issue(1, 32);

    // prologue: reduce 64 row-sum partials per column (overlapped w/ prefetch)
    if (tid < 128) {
        const int n = j0 + tid;
        float s = 0.f;
        #pragma unroll
        for (int sl = 0; sl < NSLOT; sl++)
            s += g_lp[((size_t)b * NSLOT + sl) * NN + n];
        linv_s[tid] = 1.0f / s;
    }

    int buf = 0;
    #pragma unroll 1
    for (int t = 0; t < KTILES; t++) {
        if (t == KTILES - 1) { CP_WAIT(0); } else { CP_WAIT(1); }
        __syncthreads();
        if (t + 2 < KTILES) {
            int pb = buf + 2; if (pb >= 3) pb -= 3;
            issue(pb, (t + 2) * 32);
        }

        const uint32_t aA = smbase + buf * S_STAGE;
        const uint32_t aB = aA + TILE_BYTES;

        #pragma unroll
        for (int ks = 0; ks < 2; ks++) {
            const uint32_t kb2 = ks * 32;
            uint32_t ahf[4][4];
            #pragma unroll
            for (int mt = 0; mt < 4; mt++) {
                const uint32_t toff = (uint32_t)((wm * 64 + mt * 16) * ROW_STRIDE) + kb2 + offA;
                LDSM_X4(ahf[mt][0], ahf[mt][1], ahf[mt][2], ahf[mt][3], aA + toff);
            }
            uint32_t bhf[4][2];
            #pragma unroll
            for (int g = 0; g < 2; g++) {
                const uint32_t toff = (uint32_t)((wn * 32 + g * 16) * ROW_STRIDE) + kb2 + offB;
                LDSM_X4(bhf[2*g][0], bhf[2*g][1], bhf[2*g+1][0], bhf[2*g+1][1], aB + toff);
            }
            #pragma unroll
            for (int mt = 0; mt < 4; mt++)
                #pragma unroll
                for (int nt = 0; nt < 4; nt++)
                    MMA16816(acc[mt][nt], ahf[mt], bhf[nt][0], bhf[nt][1]);
        }

        buf = (buf + 1 == 3) ? 0 : buf + 1;
    }

    const int g  = lane >> 2;
    const int tq = lane & 3;
    float* Cb = C + (size_t)b * sC;
    const float* Rb = R + (size_t)b * sC;

    #pragma unroll
    for (int mt = 0; mt < 4; mt++) {
        const int row0 = i0 + wm * 64 + mt * 16 + g;
        #pragma unroll
        for (int nt = 0; nt < 4; nt++) {
            const int lcol = wn * 32 + nt * 8 + tq * 2;
            const int col  = j0 + lcol;
            const float2 li = *(const float2*)&linv_s[lcol];
            float2 v0 = make_float2(acc[mt][nt][0] * li.x, acc[mt][nt][1] * li.y);
            float2 v1 = make_float2(acc[mt][nt][2] * li.x, acc[mt][nt][3] * li.y);
            const size_t idx0 = (size_t)row0 * ldc + col;
            const size_t idx1 = (size_t)(row0 + 8) * ldc + col;
            float2 r0 = *(const float2*)&Rb[idx0];
            float2 r1 = *(const float2*)&Rb[idx1];
            v0.x += r0.x; v0.y += r0.y; v1.x += r1.x; v1.y += r1.y;
            *(float2*)&Cb[idx0] = v0;
            *(float2*)&Cb[idx1] = v1;
        }
    }
}

// ---------------------------------------------------------------------------
extern "C" void kernel_launch(void* const* d_in, const int* in_sizes, int n_in,
                              void* d_out, int out_size)
{
    const float* x  = (const float*)d_in[0];
    const float* Wq = (const float*)d_in[1];
    const float* bq = (const float*)d_in[2];
    const float* Wk = (const float*)d_in[3];
    const float* bk = (const float*)d_in[4];
    const float* Wv = (const float*)d_in[5];
    const float* bv = (const float*)d_in[6];
    float* out = (float*)d_out;

    void *pQh, *pKh, *pVh, *pPh;
    cudaGetSymbolAddress(&pQh, g_Qh);
    cudaGetSymbolAddress(&pKh, g_Kh);
    cudaGetSymbolAddress(&pVh, g_Vh);
    cudaGetSymbolAddress(&pPh, g_Ph);

    cudaFuncSetAttribute(qkv_mma,
                         cudaFuncAttributeMaxDynamicSharedMemorySize, QSMEM);
    cudaFuncSetAttribute((const void*)score_gemm<CC / 32>,
                         cudaFuncAttributeMaxDynamicSharedMemorySize, G_SMEM);
    cudaFuncSetAttribute((const void*)out_gemm<NN / 32>,
                         cudaFuncAttributeMaxDynamicSharedMemorySize, G_SMEM);

    xsplit_kernel<<<dim3(NN / 32, CC / 32, BB), 256>>>(x);
    wsplit_kernel<<<dim3(CC, 3), 256>>>(Wq, Wk, Wv);
    qkv_mma<<<dim3(NN / 128, CC / 64, BB), 256, QSMEM>>>(bq, bk, bv);

    // scores + exp: Ph[n][m] = exp(Q.K/16), per-slot row partials to g_lp
    score_gemm<CC / 32><<<dim3(NN / 128, NN / 128, BB), 256, G_SMEM>>>(
        (const __nv_bfloat16*)pQh, (const __nv_bfloat16*)pKh,
        CC, CC, NN, 1.0f / 16.0f,
        (size_t)NN * CC, (size_t)NN * CC, (size_t)NN * NN);

    // out: C[c][n] = linv[n] * (V[c][:] . Ph[n][:]) + x   (linv from g_lp)
    out_gemm<NN / 32><<<dim3(NN / 128, CC / 128, BB), 256, G_SMEM>>>(
        (const __nv_bfloat16*)pVh, (const __nv_bfloat16*)pPh,
        out, x,
        NN, NN, NN,
        (size_t)CC * NN, (size_t)NN * NN, (size_t)CC * NN);
}